// round 1
// baseline (speedup 1.0000x reference)
#include <cuda_runtime.h>
#include <cstdint>

typedef unsigned long long ull;

#define NEXP     16
#define DIM      256
#define PP       64
#define TCHUNK   2048
#define MT       128
#define KC       64
#define XS       (KC + 4)     // x_s row stride (floats) = 68 -> bank-safe, 16B aligned
#define NTHREADS 256

// ---- packed f32x2 helpers (Blackwell FFMA2 path) ----
__device__ __forceinline__ ull pack_dup(float a) {
    ull r;
    asm("mov.b64 %0, {%1, %2};" : "=l"(r) : "f"(a), "f"(a));
    return r;
}
__device__ __forceinline__ void ffma2(ull& d, ull a, ull b) {
    asm("fma.rn.f32x2 %0, %1, %2, %0;" : "+l"(d) : "l"(a), "l"(b));
}
__device__ __forceinline__ float2 unpack2(ull v) {
    float2 r;
    asm("mov.b64 {%0, %1}, %2;" : "=f"(r.x), "=f"(r.y) : "l"(v));
    return r;
}

// Inner FMA over one K-chunk, specialized on number of active m-groups (1..4).
template <int NG>
__device__ __forceinline__ void fma_chunk(ull (&acc)[4][4], const float* __restrict__ x_s,
                                          const float* __restrict__ b_base, int mb) {
    #pragma unroll 8
    for (int k = 0; k < KC; k++) {
        const float* brow = b_base + k * PP;           // + tn8 already folded in b_base
        ulonglong2 bA = *(const ulonglong2*)(brow);    // n pairs {0,1},{2,3}
        ulonglong2 bB = *(const ulonglong2*)(brow + 4);// n pairs {4,5},{6,7}
        #pragma unroll
        for (int i = 0; i < NG; i++) {
            ull aa = pack_dup(x_s[(mb + 32 * i) * XS + k]);
            ffma2(acc[i][0], aa, bA.x);
            ffma2(acc[i][1], aa, bA.y);
            ffma2(acc[i][2], aa, bB.x);
            ffma2(acc[i][3], aa, bB.y);
        }
    }
}

extern __shared__ char smem_raw[];

__global__ __launch_bounds__(NTHREADS, 2)
void moe_pixels_kernel(const float* __restrict__ x,
                       const float* __restrict__ W,
                       const float* __restrict__ bias,
                       const int*   __restrict__ bidx,
                       float*       __restrict__ out,
                       int n_tokens)
{
    float* b_s    = (float*)smem_raw;             // [DIM][PP]  = 16384 f32 (64 KB)
    float* x_s    = b_s + DIM * PP;               // [MT][XS]   = 8704  f32 (34 KB)
    int*   s_rows = (int*)(x_s + MT * XS);        // [TCHUNK]   (8 KB)
    __shared__ int s_cnt;

    const int tid  = threadIdx.x;
    const int e    = blockIdx.y;
    const int base = blockIdx.x * TCHUNK;

    if (tid == 0) s_cnt = 0;
    __syncthreads();

    // ---- Phase 1: select tokens routed to expert e in this chunk ----
    int lim = n_tokens - base;
    if (lim > TCHUNK) lim = TCHUNK;
    for (int i = tid; i < lim; i += NTHREADS) {
        if (bidx[base + i] == e) {
            int pos = atomicAdd(&s_cnt, 1);
            s_rows[pos] = base + i;
        }
    }

    // ---- Phase 2: stage W[e] ([DIM][PP], K-major) into smem ----
    {
        const float4* src = (const float4*)(W + (size_t)e * DIM * PP);
        float4* dst = (float4*)b_s;
        #pragma unroll
        for (int i = 0; i < (DIM * PP / 4) / NTHREADS; i++)     // 16 iters
            dst[tid + i * NTHREADS] = src[tid + i * NTHREADS];
    }
    __syncthreads();

    const int cnt = s_cnt;
    if (cnt == 0) return;

    // Thread tile: 4 m (strided by 32) x 8 n (contiguous).
    const int mb  = tid >> 3;          // 0..31
    const int tn8 = (tid & 7) * 8;     // n base 0..56

    const float4 bv0 = *(const float4*)(bias + e * PP + tn8);
    const float4 bv1 = *(const float4*)(bias + e * PP + tn8 + 4);

    // x staging map: 16 threads per row, 16 rows per pass
    const int lr = tid >> 4;           // 0..15
    const int lc = (tid & 15) * 4;     // float4 col offset within K-chunk

    for (int m0 = 0; m0 < cnt; m0 += MT) {
        int mcount = cnt - m0;
        if (mcount > MT) mcount = MT;
        const int ngrp = (mcount + 31) >> 5;   // active m-groups: 1..4

        ull acc[4][4];
        #pragma unroll
        for (int i = 0; i < 4; i++)
            #pragma unroll
            for (int j = 0; j < 4; j++) acc[i][j] = 0ULL;

        for (int kk = 0; kk < DIM; kk += KC) {
            __syncthreads();   // previous chunk's readers done
            #pragma unroll
            for (int p = 0; p < MT / 16; p++) {
                int m = lr + p * 16;
                float4 v = make_float4(0.f, 0.f, 0.f, 0.f);
                if (m < mcount)
                    v = *(const float4*)(x + (size_t)s_rows[m0 + m] * DIM + kk + lc);
                *(float4*)(x_s + m * XS + lc) = v;
            }
            __syncthreads();

            const float* b_base = b_s + kk * PP + tn8;
            switch (ngrp) {
                case 1: fma_chunk<1>(acc, x_s, b_base, mb); break;
                case 2: fma_chunk<2>(acc, x_s, b_base, mb); break;
                case 3: fma_chunk<3>(acc, x_s, b_base, mb); break;
                default: fma_chunk<4>(acc, x_s, b_base, mb); break;
            }
        }

        // ---- Epilogue: bias + scattered row writes ----
        #pragma unroll
        for (int i = 0; i < 4; i++) {
            int m = mb + 32 * i;
            if (m < mcount) {
                float* o = out + (size_t)s_rows[m0 + m] * PP + tn8;
                float2 p0 = unpack2(acc[i][0]);
                float2 p1 = unpack2(acc[i][1]);
                float2 p2 = unpack2(acc[i][2]);
                float2 p3 = unpack2(acc[i][3]);
                float4 r0 = make_float4(p0.x + bv0.x, p0.y + bv0.y,
                                        p1.x + bv0.z, p1.y + bv0.w);
                float4 r1 = make_float4(p2.x + bv1.x, p2.y + bv1.y,
                                        p3.x + bv1.z, p3.y + bv1.w);
                *(float4*)(o)     = r0;
                *(float4*)(o + 4) = r1;
            }
        }
    }
}

extern "C" void kernel_launch(void* const* d_in, const int* in_sizes, int n_in,
                              void* d_out, int out_size) {
    const float* x    = (const float*)d_in[0];
    const float* W    = (const float*)d_in[1];
    const float* bias = (const float*)d_in[2];
    const int*   idx  = (const int*)d_in[3];
    float*       out  = (float*)d_out;

    const int n_tokens = in_sizes[3];

    const int smem_bytes = (DIM * PP + MT * XS) * 4 + TCHUNK * 4;   // 108,544 B
    cudaFuncSetAttribute(moe_pixels_kernel,
                         cudaFuncAttributeMaxDynamicSharedMemorySize, smem_bytes);

    dim3 grid((n_tokens + TCHUNK - 1) / TCHUNK, NEXP);
    moe_pixels_kernel<<<grid, NTHREADS, smem_bytes>>>(x, W, bias, idx, out, n_tokens);
}